// round 10
// baseline (speedup 1.0000x reference)
#include <cuda_runtime.h>
#include <cstdint>
#include <cub/cub.cuh>

// ---------------------------------------------------------------------------
// ProposalLayer: B=4, A=9, H=50, W=76, FEAT_STRIDE=16
// pre-NMS topN = 6000, post-NMS topN = 300, nms thresh = 0.7
// R10 = R8 mask+reduce (best known) with the entire front-end (decode +
// device radix sort + gather, ~7 launches) replaced by ONE fused
// counting-sort selection kernel per image.
// ---------------------------------------------------------------------------

#define BATCH     4
#define A_NUM     9
#define H_DIM     50
#define W_DIM     76
#define HW_DIM    (H_DIM * W_DIM)          // 3800
#define N_ANCH    (A_NUM * HW_DIM)         // 34200
#define PRE_TOPN  6000
#define POST_TOPN 300
#define NMS_TH    0.7f
#define NWORDS    94                        // ceil(6000/64)
#define TAIL_BITS 48                        // 6000 - 93*64
#define NBUCKET   16384                     // top-14 bits of 30-bit desc score
#define CAP       8192                      // selected-key buffer capacity

typedef unsigned long long u64;

// Precomputed generate_anchors(base=16, ratios={0.5,1,2}, scales={8,16,32})
__constant__ float c_anchors[A_NUM * 4] = {
    -84.f,  -40.f,   99.f,   55.f,
   -176.f,  -88.f,  191.f,  103.f,
   -360.f, -184.f,  375.f,  199.f,
    -56.f,  -56.f,   71.f,   71.f,
   -120.f, -120.f,  135.f,  135.f,
   -248.f, -248.f,  263.f,  263.f,
    -36.f,  -80.f,   51.f,   95.f,
    -80.f, -168.f,   95.f,  183.f,
   -168.f, -344.f,  183.f,  359.f
};

// Device-global scratch (no runtime allocation allowed)
__device__ float4 g_sboxes  [BATCH][PRE_TOPN];
__device__ float  g_sareas  [BATCH][PRE_TOPN];
__device__ u64    g_mask    [BATCH][PRE_TOPN][NWORDS];

// ---------------------------------------------------------------------------
// Kernel 1 (fused): select top-6000 per image in EXACT stable order + decode.
// One CTA of 1024 threads per image. 46-bit key = [desc30:30 | idx:16];
// numeric order of the full key == stable argsort(-score) order (idx breaks
// ties ascending). Counting sort: 16384-bucket histogram on the top 14 key
// bits, exclusive scan -> cutoff bucket B* (cumsum crosses 6000), scatter
// selected keys to their global rank, tiny per-bucket insertion sorts fix
// within-bucket order. Then decode/clip ONLY the top-6000 boxes.
// Capacity clip at 8192 provably cannot disturb ranks < 6000: a clipped
// key's bucket span starts at rank >= 8192 - cnt, far beyond 6000.
// ---------------------------------------------------------------------------
__global__ void __launch_bounds__(1024, 1)
select_kernel(const float* __restrict__ scores,
              const float* __restrict__ deltas,
              const float* __restrict__ im_info)
{
    int b = blockIdx.x;
    int t = threadIdx.x;
    extern __shared__ unsigned char sm[];
    unsigned* hist = (unsigned*)sm;               // 16384 * 4B
    u64*      keys = (u64*)(hist + NBUCKET);      // 8192 * 8B
    __shared__ int s_Bstar;
    __shared__ typename cub::BlockScan<unsigned, 1024>::TempStorage scan_ts;

    for (int q = t; q < NBUCKET; q += 1024) hist[q] = 0;
    for (int q = t; q < CAP;     q += 1024) keys[q] = ~0ull;
    __syncthreads();

    // objectness scores for image b: layout [a][hw], a in [0,9)
    const float* sc_base = scores + ((size_t)b * 2 * A_NUM + A_NUM) * HW_DIM;

    // Pass A: histogram (m = a*HW + hw, coalesced)
    for (int m = t; m < N_ANCH; m += 1024) {
        unsigned u = __float_as_uint(sc_base[m]);
        u = min(u, 0x3F7FFFFFu);                  // uniform [0,1) => 30 bits
        atomicAdd(&hist[(0x3F7FFFFFu - u) >> 16], 1u);
    }
    __syncthreads();

    // Exclusive scan over buckets; find B* (cumsum crosses PRE_TOPN).
    // Thread t owns contiguous buckets [t*16, t*16+16).
    unsigned cnt[16], sum = 0;
    #pragma unroll
    for (int k = 0; k < 16; k++) { cnt[k] = hist[t * 16 + k]; sum += cnt[k]; }
    unsigned ex_base;
    cub::BlockScan<unsigned, 1024>(scan_ts).ExclusiveSum(sum, ex_base);
    unsigned run = ex_base;
    #pragma unroll
    for (int k = 0; k < 16; k++) {
        unsigned inc = run + cnt[k];
        if (run < PRE_TOPN && inc >= PRE_TOPN) s_Bstar = t * 16 + k;
        hist[t * 16 + k] = run;                   // exclusive cumsum in place
        run = inc;
    }
    __syncthreads();
    int Bstar = s_Bstar;

    // Pass B: scatter selected keys to their global-rank slot.
    for (int m = t; m < N_ANCH; m += 1024) {
        unsigned u = __float_as_uint(sc_base[m]);
        u = min(u, 0x3F7FFFFFu);
        unsigned d   = 0x3F7FFFFFu - u;
        unsigned bkt = d >> 16;
        if ((int)bkt <= Bstar) {
            int a = m / HW_DIM, hw = m - a * HW_DIM;
            unsigned idx = (unsigned)(hw * A_NUM + a);   // reference flatten
            int slot = (int)atomicAdd(&hist[bkt], 1u);
            if (slot < CAP) keys[slot] = ((u64)d << 16) | idx;
        }
    }
    __syncthreads();

    // Per-bucket insertion sort (spans avg ~2). After pass B, hist[q] for
    // q <= B* is the inclusive cumsum; span(q) = [hist[q-1], hist[q]).
    for (int q = t; q <= Bstar; q += 1024) {
        int start = (q == 0) ? 0 : (int)hist[q - 1];
        int end   = (int)hist[q];
        if (end > CAP) end = CAP;
        for (int x = start + 1; x < end; x++) {
            u64 kx = keys[x];
            int y = x - 1;
            while (y >= start && keys[y] > kx) { keys[y + 1] = keys[y]; y--; }
            keys[y + 1] = kx;
        }
    }
    __syncthreads();

    // Emit: decode + clip only the exact top-6000, in final sorted order.
    float imh = im_info[b * 3 + 0];
    float imw = im_info[b * 3 + 1];
    const float* dl = deltas + (size_t)b * 4 * A_NUM * HW_DIM;

    for (int p = t; p < PRE_TOPN; p += 1024) {
        unsigned idx = (unsigned)(keys[p] & 0xFFFFull);
        int a  = idx % A_NUM;
        int hw = idx / A_NUM;
        int w  = hw % W_DIM;
        int h  = hw / W_DIM;

        float sx = (float)(w * 16);
        float sy = (float)(h * 16);
        float ax1 = c_anchors[a * 4 + 0] + sx;
        float ay1 = c_anchors[a * 4 + 1] + sy;
        float ax2 = c_anchors[a * 4 + 2] + sx;
        float ay2 = c_anchors[a * 4 + 3] + sy;

        float wa  = ax2 - ax1 + 1.0f;
        float ha  = ay2 - ay1 + 1.0f;
        float cxa = ax1 + 0.5f * wa;
        float cya = ay1 + 0.5f * ha;

        size_t dbase = (size_t)(a * 4) * HW_DIM + hw;
        float dx = dl[dbase];
        float dy = dl[dbase +     HW_DIM];
        float dw = dl[dbase + 2 * HW_DIM];
        float dh = dl[dbase + 3 * HW_DIM];

        float pcx = dx * wa + cxa;
        float pcy = dy * ha + cya;
        float pw  = expf(dw) * wa;
        float ph  = expf(dh) * ha;

        float x1 = fminf(fmaxf(pcx - 0.5f * pw, 0.0f), imw - 1.0f);
        float y1 = fminf(fmaxf(pcy - 0.5f * ph, 0.0f), imh - 1.0f);
        float x2 = fminf(fmaxf(pcx + 0.5f * pw, 0.0f), imw - 1.0f);
        float y2 = fminf(fmaxf(pcy + 0.5f * ph, 0.0f), imh - 1.0f);

        g_sboxes[b][p] = make_float4(x1, y1, x2, y2);
        g_sareas[b][p] = (x2 - x1 + 1.0f) * (y2 - y1 + 1.0f);
    }
}

// ---------------------------------------------------------------------------
// Kernel 2: suppression bitmask matrix (upper triangle only).  [R8 version]
// Block (bi, bj, b): thread t owns row i = bi*64+t, computes the 64-bit word
// of columns [bj*64, bj*64+64): bit c set iff IoU(i,j) > 0.7 and j > i.
// Multiply-form test with 1e-5 relative guard band; exact division fallback
// inside the band (decision-identical to reference).
// ---------------------------------------------------------------------------
__global__ void mask_kernel()
{
    int bi = blockIdx.x, bj = blockIdx.y, b = blockIdx.z;
    if (bj < bi) return;

    __shared__ float4 cb[64];
    __shared__ float  ca[64];
    int t  = threadIdx.x;
    int j0 = bj * 64;
    int jt = j0 + t;
    if (jt < PRE_TOPN) { cb[t] = g_sboxes[b][jt]; ca[t] = g_sareas[b][jt]; }
    __syncthreads();

    int i = bi * 64 + t;
    if (i >= PRE_TOPN) return;
    float4 bx = g_sboxes[b][i];
    float  ai = g_sareas[b][i];

    u64 bits = 0;
    int cmax = min(64, PRE_TOPN - j0);
    #pragma unroll 4
    for (int c = 0; c < cmax; c++) {
        int j = j0 + c;
        if (j <= i) continue;
        float4 bv = cb[c];
        float iw = fminf(bx.z, bv.z) - fmaxf(bx.x, bv.x) + 1.0f;
        float ih = fminf(bx.w, bv.w) - fmaxf(bx.y, bv.y) + 1.0f;
        float inter = fmaxf(iw, 0.0f) * fmaxf(ih, 0.0f);
        float u  = ai + ca[c] - inter;
        float diff = inter - NMS_TH * u;
        bool sup;
        if (fabsf(diff) > 1e-5f * u) sup = (diff > 0.0f);       // fast path
        else                         sup = (inter / u) > NMS_TH; // exact (rare)
        if (sup) bits |= (1ull << c);
    }
    g_mask[b][i][bj] = bits;
}

// ---------------------------------------------------------------------------
// Kernel 3: greedy reduce — ONE WARP per image, barrier-free.  [R8 version]
// removed-bitmask lives in registers (3 x u64 per lane; lane l owns words
// 3l, 3l+1, 3l+2). Kept bits are also marked removed, so the next kept box is
// simply the first zero bit. Mask rows are software-pipelined: after ORing
// row i, the next kept j1 is definitive and j2 is a ~99.7%-probability
// speculation, so row j1 is always >=1 iteration in flight (usually 2).
// ---------------------------------------------------------------------------
__global__ void __launch_bounds__(32, 1)
reduce_kernel(float* __restrict__ out)
{
    const unsigned FULL = 0xFFFFFFFFu;
    int b = blockIdx.x;
    int l = threadIdx.x;

    // validity masks for owned words
    u64 vm[3];
    #pragma unroll
    for (int s = 0; s < 3; s++) {
        int w = 3 * l + s;
        vm[s] = (w < NWORDS - 1) ? ~0ull
              : (w == NWORDS - 1 ? ((1ull << TAIL_BITS) - 1ull) : 0ull);
    }
    u64 removed[3] = {0, 0, 0};

    // Pre-fill output rows: [b, 0,0,0,0] (d_out arrives poisoned).
    for (int j = l; j < POST_TOPN * 5; j += 32) {
        int r = j / 5, c = j % 5;
        out[((size_t)b * POST_TOPN + r) * 5 + c] = (c == 0) ? (float)b : 0.0f;
    }

    const u64* maskb = &g_mask[b][0][0];

    // load row j, zeroed below its diagonal word and outside [0,NWORDS)
    auto load_row = [&](int j, u64* r) {
        int wlo = j >> 6;
        const u64* rp = maskb + (size_t)j * NWORDS;
        #pragma unroll
        for (int s = 0; s < 3; s++) {
            int w = 3 * l + s;
            r[s] = (w < NWORDS && w >= wlo) ? rp[w] : 0ull;
        }
    };
    // first set bit among lanes' alive words; all lanes get the same value
    auto find_first = [&](u64 a0, u64 a1, u64 a2) -> int {
        int fs = a0 ? 0 : (a1 ? 1 : (a2 ? 2 : 3));
        unsigned ball = __ballot_sync(FULL, fs < 3);
        if (!ball) return -1;
        int L   = __ffs(ball) - 1;
        int fsL = __shfl_sync(FULL, fs, L);
        u64 w0 = __shfl_sync(FULL, a0, L);
        u64 w1 = __shfl_sync(FULL, a1, L);
        u64 w2 = __shfl_sync(FULL, a2, L);
        u64 fa = (fsL == 0) ? w0 : ((fsL == 1) ? w1 : w2);
        return (L * 3 + fsL) * 64 + __ffsll((long long)fa) - 1;
    };

    // bootstrap: candidate 0 is always the first kept box
    int i = 0;
    u64 row[3];
    load_row(0, row);
    float4 pb = g_sboxes[b][0];     // broadcast load
    int idx2 = -1;
    u64 spec[3] = {0, 0, 0};

    int count = 0;
    while (true) {
        // emit current kept box
        if (l == 0) {
            float* o = out + ((size_t)b * POST_TOPN + count) * 5;
            o[1] = pb.x; o[2] = pb.y; o[3] = pb.z; o[4] = pb.w;
        }
        count++;
        if (count == POST_TOPN) break;

        // fold suppression row of i, mark i itself removed
        removed[0] |= row[0];
        removed[1] |= row[1];
        removed[2] |= row[2];
        int wi = i >> 6;
        int sl = wi - 3 * l;
        if (sl >= 0 && sl < 3) removed[sl] |= 1ull << (i & 63);

        // j1 = definitive next kept; j2 = speculative next-next
        u64 a0 = ~removed[0] & vm[0];
        u64 a1 = ~removed[1] & vm[1];
        u64 a2 = ~removed[2] & vm[2];
        int j1 = find_first(a0, a1, a2);
        if (j1 < 0) break;
        int s1 = (j1 >> 6) - 3 * l;
        u64 bm = 1ull << (j1 & 63);
        if (s1 == 0) a0 &= ~bm; else if (s1 == 1) a1 &= ~bm;
        else if (s1 == 2) a2 &= ~bm;
        int j2 = find_first(a0, a1, a2);

        // row for j1: promoted from speculation (usual) or fresh load (rare)
        u64 nrow[3];
        if (j1 == idx2) {
            nrow[0] = spec[0]; nrow[1] = spec[1]; nrow[2] = spec[2];
        } else {
            load_row(j1, nrow);
        }
        float4 npb = g_sboxes[b][j1];          // box prefetch (always exact)

        // issue speculative load for j2
        if (j2 >= 0) { load_row(j2, spec); idx2 = j2; }
        else idx2 = -1;

        i = j1;
        row[0] = nrow[0]; row[1] = nrow[1]; row[2] = nrow[2];
        pb = npb;
    }
}

// ---------------------------------------------------------------------------
// Launch
// ---------------------------------------------------------------------------
extern "C" void kernel_launch(void* const* d_in, const int* in_sizes, int n_in,
                              void* d_out, int out_size)
{
    const float* scores  = (const float*)d_in[0];   // (4, 18, 50, 76)
    const float* deltas  = (const float*)d_in[1];   // (4, 36, 50, 76)
    const float* im_info = (const float*)d_in[2];   // (4, 3)
    float*       out     = (float*)d_out;           // (4, 300, 5)

    size_t smem = (size_t)NBUCKET * sizeof(unsigned) + (size_t)CAP * sizeof(u64);
    cudaFuncSetAttribute(select_kernel,
                         cudaFuncAttributeMaxDynamicSharedMemorySize,
                         (int)smem);
    select_kernel<<<BATCH, 1024, smem>>>(scores, deltas, im_info);

    dim3 mgrid(NWORDS, NWORDS, BATCH);
    mask_kernel<<<mgrid, 64>>>();

    reduce_kernel<<<BATCH, 32>>>(out);
}

// round 11
// speedup vs baseline: 2.4158x; 2.4158x over previous
#include <cuda_runtime.h>
#include <cstdint>
#include <cub/cub.cuh>

// ---------------------------------------------------------------------------
// ProposalLayer: B=4, A=9, H=50, W=76, FEAT_STRIDE=16
// pre-NMS topN = 6000, post-NMS topN = 300, nms thresh = 0.7
// R11 = R10 with the select kernel's buckets computed on the score VALUE
// (uniform occupancy, Poisson lambda~2.1) instead of float bit patterns
// (which concentrated ~134 keys/bucket and made insertion sort O(n^2)-slow).
// ---------------------------------------------------------------------------

#define BATCH     4
#define A_NUM     9
#define H_DIM     50
#define W_DIM     76
#define HW_DIM    (H_DIM * W_DIM)          // 3800
#define N_ANCH    (A_NUM * HW_DIM)         // 34200
#define PRE_TOPN  6000
#define POST_TOPN 300
#define NMS_TH    0.7f
#define NWORDS    94                        // ceil(6000/64)
#define TAIL_BITS 48                        // 6000 - 93*64
#define NBUCKET   16384
#define CAP       8192                      // selected-key buffer capacity

typedef unsigned long long u64;

// Precomputed generate_anchors(base=16, ratios={0.5,1,2}, scales={8,16,32})
__constant__ float c_anchors[A_NUM * 4] = {
    -84.f,  -40.f,   99.f,   55.f,
   -176.f,  -88.f,  191.f,  103.f,
   -360.f, -184.f,  375.f,  199.f,
    -56.f,  -56.f,   71.f,   71.f,
   -120.f, -120.f,  135.f,  135.f,
   -248.f, -248.f,  263.f,  263.f,
    -36.f,  -80.f,   51.f,   95.f,
    -80.f, -168.f,   95.f,  183.f,
   -168.f, -344.f,  183.f,  359.f
};

// Device-global scratch (no runtime allocation allowed)
__device__ float4 g_sboxes  [BATCH][PRE_TOPN];
__device__ float  g_sareas  [BATCH][PRE_TOPN];
__device__ u64    g_mask    [BATCH][PRE_TOPN][NWORDS];

// Descending value-bucket: monotone non-decreasing in d (= score descending).
// floor(sc*N) is monotone in sc (positive-const multiply + floor), so coarse
// bucket order is exact; within-bucket order fixed by the full key.
__device__ __forceinline__ int score_bucket(float sc) {
    int f = (int)(sc * (float)NBUCKET);
    f = min(max(f, 0), NBUCKET - 1);
    return (NBUCKET - 1) - f;
}

// ---------------------------------------------------------------------------
// Kernel 1 (fused): select top-6000 per image in EXACT stable order + decode.
// One CTA of 1024 threads per image. 46-bit key = [desc30:30 | idx:16];
// numeric order of the full key == stable argsort(-score) (idx breaks ties
// ascending). Counting sort over 16384 VALUE buckets: histogram, exclusive
// scan -> cutoff bucket B* (cumsum crosses 6000), scatter selected keys to
// their global rank, per-bucket insertion sorts (span ~2) fix within-bucket
// order by full key. Then decode/clip ONLY the top-6000 boxes.
// Capacity clip at 8192 cannot disturb ranks < 6000 (clipped keys sit at
// rank >= CAP - span, far beyond 6000).
// ---------------------------------------------------------------------------
__global__ void __launch_bounds__(1024, 1)
select_kernel(const float* __restrict__ scores,
              const float* __restrict__ deltas,
              const float* __restrict__ im_info)
{
    int b = blockIdx.x;
    int t = threadIdx.x;
    extern __shared__ unsigned char sm[];
    unsigned* hist = (unsigned*)sm;               // 16384 * 4B
    u64*      keys = (u64*)(hist + NBUCKET);      // 8192 * 8B
    __shared__ int s_Bstar;
    __shared__ typename cub::BlockScan<unsigned, 1024>::TempStorage scan_ts;

    for (int q = t; q < NBUCKET; q += 1024) hist[q] = 0;
    for (int q = t; q < CAP;     q += 1024) keys[q] = ~0ull;
    __syncthreads();

    // objectness scores for image b: layout [a][hw], a in [0,9)
    const float* sc_base = scores + ((size_t)b * 2 * A_NUM + A_NUM) * HW_DIM;

    // Pass A: histogram on value buckets (m = a*HW + hw, coalesced)
    for (int m = t; m < N_ANCH; m += 1024) {
        atomicAdd(&hist[score_bucket(sc_base[m])], 1u);
    }
    __syncthreads();

    // Exclusive scan over buckets; find B* (cumsum crosses PRE_TOPN).
    // Thread t owns contiguous buckets [t*16, t*16+16).
    unsigned cnt[16], sum = 0;
    #pragma unroll
    for (int k = 0; k < 16; k++) { cnt[k] = hist[t * 16 + k]; sum += cnt[k]; }
    unsigned ex_base;
    cub::BlockScan<unsigned, 1024>(scan_ts).ExclusiveSum(sum, ex_base);
    unsigned run = ex_base;
    #pragma unroll
    for (int k = 0; k < 16; k++) {
        unsigned inc = run + cnt[k];
        if (run < PRE_TOPN && inc >= PRE_TOPN) s_Bstar = t * 16 + k;
        hist[t * 16 + k] = run;                   // exclusive cumsum in place
        run = inc;
    }
    __syncthreads();
    int Bstar = s_Bstar;

    // Pass B: scatter selected keys to their global-rank slot.
    for (int m = t; m < N_ANCH; m += 1024) {
        float sc = sc_base[m];
        int bkt = score_bucket(sc);
        if (bkt <= Bstar) {
            unsigned u = __float_as_uint(sc);
            u = min(u, 0x3F7FFFFFu);              // uniform [0,1) => 30 bits
            unsigned d = 0x3F7FFFFFu - u;
            int a = m / HW_DIM, hw = m - a * HW_DIM;
            unsigned idx = (unsigned)(hw * A_NUM + a);   // reference flatten
            int slot = (int)atomicAdd(&hist[bkt], 1u);
            if (slot < CAP) keys[slot] = ((u64)d << 16) | idx;
        }
    }
    __syncthreads();

    // Per-bucket insertion sort (spans ~Poisson(2.1), max ~13). After pass B,
    // hist[q] for q <= B* is the inclusive cumsum; span(q) = [hist[q-1], hist[q]).
    for (int q = t; q <= Bstar; q += 1024) {
        int start = (q == 0) ? 0 : (int)hist[q - 1];
        int end   = (int)hist[q];
        if (end > CAP) end = CAP;
        for (int x = start + 1; x < end; x++) {
            u64 kx = keys[x];
            int y = x - 1;
            while (y >= start && keys[y] > kx) { keys[y + 1] = keys[y]; y--; }
            keys[y + 1] = kx;
        }
    }
    __syncthreads();

    // Emit: decode + clip only the exact top-6000, in final sorted order.
    float imh = im_info[b * 3 + 0];
    float imw = im_info[b * 3 + 1];
    const float* dl = deltas + (size_t)b * 4 * A_NUM * HW_DIM;

    for (int p = t; p < PRE_TOPN; p += 1024) {
        unsigned idx = (unsigned)(keys[p] & 0xFFFFull);
        int a  = idx % A_NUM;
        int hw = idx / A_NUM;
        int w  = hw % W_DIM;
        int h  = hw / W_DIM;

        float sx = (float)(w * 16);
        float sy = (float)(h * 16);
        float ax1 = c_anchors[a * 4 + 0] + sx;
        float ay1 = c_anchors[a * 4 + 1] + sy;
        float ax2 = c_anchors[a * 4 + 2] + sx;
        float ay2 = c_anchors[a * 4 + 3] + sy;

        float wa  = ax2 - ax1 + 1.0f;
        float ha  = ay2 - ay1 + 1.0f;
        float cxa = ax1 + 0.5f * wa;
        float cya = ay1 + 0.5f * ha;

        size_t dbase = (size_t)(a * 4) * HW_DIM + hw;
        float dx = dl[dbase];
        float dy = dl[dbase +     HW_DIM];
        float dw = dl[dbase + 2 * HW_DIM];
        float dh = dl[dbase + 3 * HW_DIM];

        float pcx = dx * wa + cxa;
        float pcy = dy * ha + cya;
        float pw  = expf(dw) * wa;
        float ph  = expf(dh) * ha;

        float x1 = fminf(fmaxf(pcx - 0.5f * pw, 0.0f), imw - 1.0f);
        float y1 = fminf(fmaxf(pcy - 0.5f * ph, 0.0f), imh - 1.0f);
        float x2 = fminf(fmaxf(pcx + 0.5f * pw, 0.0f), imw - 1.0f);
        float y2 = fminf(fmaxf(pcy + 0.5f * ph, 0.0f), imh - 1.0f);

        g_sboxes[b][p] = make_float4(x1, y1, x2, y2);
        g_sareas[b][p] = (x2 - x1 + 1.0f) * (y2 - y1 + 1.0f);
    }
}

// ---------------------------------------------------------------------------
// Kernel 2: suppression bitmask matrix (upper triangle only).  [R8 version]
// Block (bi, bj, b): thread t owns row i = bi*64+t, computes the 64-bit word
// of columns [bj*64, bj*64+64): bit c set iff IoU(i,j) > 0.7 and j > i.
// Multiply-form test with 1e-5 relative guard band; exact division fallback
// inside the band (decision-identical to reference).
// ---------------------------------------------------------------------------
__global__ void mask_kernel()
{
    int bi = blockIdx.x, bj = blockIdx.y, b = blockIdx.z;
    if (bj < bi) return;

    __shared__ float4 cb[64];
    __shared__ float  ca[64];
    int t  = threadIdx.x;
    int j0 = bj * 64;
    int jt = j0 + t;
    if (jt < PRE_TOPN) { cb[t] = g_sboxes[b][jt]; ca[t] = g_sareas[b][jt]; }
    __syncthreads();

    int i = bi * 64 + t;
    if (i >= PRE_TOPN) return;
    float4 bx = g_sboxes[b][i];
    float  ai = g_sareas[b][i];

    u64 bits = 0;
    int cmax = min(64, PRE_TOPN - j0);
    #pragma unroll 4
    for (int c = 0; c < cmax; c++) {
        int j = j0 + c;
        if (j <= i) continue;
        float4 bv = cb[c];
        float iw = fminf(bx.z, bv.z) - fmaxf(bx.x, bv.x) + 1.0f;
        float ih = fminf(bx.w, bv.w) - fmaxf(bx.y, bv.y) + 1.0f;
        float inter = fmaxf(iw, 0.0f) * fmaxf(ih, 0.0f);
        float u  = ai + ca[c] - inter;
        float diff = inter - NMS_TH * u;
        bool sup;
        if (fabsf(diff) > 1e-5f * u) sup = (diff > 0.0f);       // fast path
        else                         sup = (inter / u) > NMS_TH; // exact (rare)
        if (sup) bits |= (1ull << c);
    }
    g_mask[b][i][bj] = bits;
}

// ---------------------------------------------------------------------------
// Kernel 3: greedy reduce — ONE WARP per image, barrier-free.  [R8 version]
// removed-bitmask lives in registers (3 x u64 per lane; lane l owns words
// 3l, 3l+1, 3l+2). Kept bits are also marked removed, so the next kept box is
// simply the first zero bit. Mask rows are software-pipelined: after ORing
// row i, the next kept j1 is definitive and j2 is a ~99.7%-probability
// speculation, so row j1 is always >=1 iteration in flight (usually 2).
// ---------------------------------------------------------------------------
__global__ void __launch_bounds__(32, 1)
reduce_kernel(float* __restrict__ out)
{
    const unsigned FULL = 0xFFFFFFFFu;
    int b = blockIdx.x;
    int l = threadIdx.x;

    // validity masks for owned words
    u64 vm[3];
    #pragma unroll
    for (int s = 0; s < 3; s++) {
        int w = 3 * l + s;
        vm[s] = (w < NWORDS - 1) ? ~0ull
              : (w == NWORDS - 1 ? ((1ull << TAIL_BITS) - 1ull) : 0ull);
    }
    u64 removed[3] = {0, 0, 0};

    // Pre-fill output rows: [b, 0,0,0,0] (d_out arrives poisoned).
    for (int j = l; j < POST_TOPN * 5; j += 32) {
        int r = j / 5, c = j % 5;
        out[((size_t)b * POST_TOPN + r) * 5 + c] = (c == 0) ? (float)b : 0.0f;
    }

    const u64* maskb = &g_mask[b][0][0];

    // load row j, zeroed below its diagonal word and outside [0,NWORDS)
    auto load_row = [&](int j, u64* r) {
        int wlo = j >> 6;
        const u64* rp = maskb + (size_t)j * NWORDS;
        #pragma unroll
        for (int s = 0; s < 3; s++) {
            int w = 3 * l + s;
            r[s] = (w < NWORDS && w >= wlo) ? rp[w] : 0ull;
        }
    };
    // first set bit among lanes' alive words; all lanes get the same value
    auto find_first = [&](u64 a0, u64 a1, u64 a2) -> int {
        int fs = a0 ? 0 : (a1 ? 1 : (a2 ? 2 : 3));
        unsigned ball = __ballot_sync(FULL, fs < 3);
        if (!ball) return -1;
        int L   = __ffs(ball) - 1;
        int fsL = __shfl_sync(FULL, fs, L);
        u64 w0 = __shfl_sync(FULL, a0, L);
        u64 w1 = __shfl_sync(FULL, a1, L);
        u64 w2 = __shfl_sync(FULL, a2, L);
        u64 fa = (fsL == 0) ? w0 : ((fsL == 1) ? w1 : w2);
        return (L * 3 + fsL) * 64 + __ffsll((long long)fa) - 1;
    };

    // bootstrap: candidate 0 is always the first kept box
    int i = 0;
    u64 row[3];
    load_row(0, row);
    float4 pb = g_sboxes[b][0];     // broadcast load
    int idx2 = -1;
    u64 spec[3] = {0, 0, 0};

    int count = 0;
    while (true) {
        // emit current kept box
        if (l == 0) {
            float* o = out + ((size_t)b * POST_TOPN + count) * 5;
            o[1] = pb.x; o[2] = pb.y; o[3] = pb.z; o[4] = pb.w;
        }
        count++;
        if (count == POST_TOPN) break;

        // fold suppression row of i, mark i itself removed
        removed[0] |= row[0];
        removed[1] |= row[1];
        removed[2] |= row[2];
        int wi = i >> 6;
        int sl = wi - 3 * l;
        if (sl >= 0 && sl < 3) removed[sl] |= 1ull << (i & 63);

        // j1 = definitive next kept; j2 = speculative next-next
        u64 a0 = ~removed[0] & vm[0];
        u64 a1 = ~removed[1] & vm[1];
        u64 a2 = ~removed[2] & vm[2];
        int j1 = find_first(a0, a1, a2);
        if (j1 < 0) break;
        int s1 = (j1 >> 6) - 3 * l;
        u64 bm = 1ull << (j1 & 63);
        if (s1 == 0) a0 &= ~bm; else if (s1 == 1) a1 &= ~bm;
        else if (s1 == 2) a2 &= ~bm;
        int j2 = find_first(a0, a1, a2);

        // row for j1: promoted from speculation (usual) or fresh load (rare)
        u64 nrow[3];
        if (j1 == idx2) {
            nrow[0] = spec[0]; nrow[1] = spec[1]; nrow[2] = spec[2];
        } else {
            load_row(j1, nrow);
        }
        float4 npb = g_sboxes[b][j1];          // box prefetch (always exact)

        // issue speculative load for j2
        if (j2 >= 0) { load_row(j2, spec); idx2 = j2; }
        else idx2 = -1;

        i = j1;
        row[0] = nrow[0]; row[1] = nrow[1]; row[2] = nrow[2];
        pb = npb;
    }
}

// ---------------------------------------------------------------------------
// Launch
// ---------------------------------------------------------------------------
extern "C" void kernel_launch(void* const* d_in, const int* in_sizes, int n_in,
                              void* d_out, int out_size)
{
    const float* scores  = (const float*)d_in[0];   // (4, 18, 50, 76)
    const float* deltas  = (const float*)d_in[1];   // (4, 36, 50, 76)
    const float* im_info = (const float*)d_in[2];   // (4, 3)
    float*       out     = (float*)d_out;           // (4, 300, 5)

    size_t smem = (size_t)NBUCKET * sizeof(unsigned) + (size_t)CAP * sizeof(u64);
    cudaFuncSetAttribute(select_kernel,
                         cudaFuncAttributeMaxDynamicSharedMemorySize,
                         (int)smem);
    select_kernel<<<BATCH, 1024, smem>>>(scores, deltas, im_info);

    dim3 mgrid(NWORDS, NWORDS, BATCH);
    mask_kernel<<<mgrid, 64>>>();

    reduce_kernel<<<BATCH, 32>>>(out);
}

// round 12
// speedup vs baseline: 8.9385x; 3.7000x over previous
#include <cuda_runtime.h>
#include <cstdint>
#include <cub/cub.cuh>

// ---------------------------------------------------------------------------
// ProposalLayer: B=4, A=9, H=50, W=76, FEAT_STRIDE=16
// pre-NMS topN = 6000, post-NMS topN = 300, nms thresh = 0.7
// R12 = ENTIRE problem in ONE kernel, one 1024-thread CTA per image:
//   phase 1: R11 counting-sort select of top-6000 (exact stable order)
//   phase 2: decode/clip straight into SMEM (no gmem round trip)
//   phase 3: chunked candidate-vs-kept greedy NMS (work ~1.5M IoU instead of
//            the 72M all-pairs mask; terminates when 300 kept)
// Replaces the mask kernel (~200+us of 95%-discarded work) and the
// L2-latency-bound bitmask reduce.
// ---------------------------------------------------------------------------

#define BATCH     4
#define A_NUM     9
#define H_DIM     50
#define W_DIM     76
#define HW_DIM    (H_DIM * W_DIM)          // 3800
#define N_ANCH    (A_NUM * HW_DIM)         // 34200
#define PRE_TOPN  6000
#define POST_TOPN 300
#define NMS_TH    0.7f
#define NBUCKET   16384
#define CAP       8192
#define NTHREADS  1024
#define NCHUNK    94                        // ceil(6000/64)

typedef unsigned long long u64;

// SMEM layout (dynamic), bytes:
//   [0      , 65536 )  keys   u64[8192]
//   [65536  , 131072)  hist   u32[16384]   (ALIAS: dies before boxes written)
//   [65536  , 161536)  boxes  float4[6000]
//   [161536 , 185536)  areas  float[6000]
//   [185536 , 190336)  kbox   float4[300]
//   [190336 , 191536)  karea  float[300]
//   [191536 , 192048)  rows   u64[64]
//   [192048 , 192112)  dead   uchar[64]
#define SM_KEYS   0
#define SM_HIST   65536
#define SM_BOXES  65536
#define SM_AREAS  161536
#define SM_KBOX   185536
#define SM_KAREA  190336
#define SM_ROWS   191536
#define SM_DEAD   192048
#define SM_TOTAL  192112

// Precomputed generate_anchors(base=16, ratios={0.5,1,2}, scales={8,16,32})
__constant__ float c_anchors[A_NUM * 4] = {
    -84.f,  -40.f,   99.f,   55.f,
   -176.f,  -88.f,  191.f,  103.f,
   -360.f, -184.f,  375.f,  199.f,
    -56.f,  -56.f,   71.f,   71.f,
   -120.f, -120.f,  135.f,  135.f,
   -248.f, -248.f,  263.f,  263.f,
    -36.f,  -80.f,   51.f,   95.f,
    -80.f, -168.f,   95.f,  183.f,
   -168.f, -344.f,  183.f,  359.f
};

// Descending value-bucket: monotone non-decreasing in descending-score order;
// coarse order exact, within-bucket order fixed by the full 46-bit key.
__device__ __forceinline__ int score_bucket(float sc) {
    int f = (int)(sc * (float)NBUCKET);
    f = min(max(f, 0), NBUCKET - 1);
    return (NBUCKET - 1) - f;
}

// Guard-banded IoU > 0.7 test: multiply form unless within 1e-5 relative of
// the threshold, then exact reference division. Decision-identical to ref.
__device__ __forceinline__ bool iou_sup(float4 p, float ap, float4 q, float aq) {
    float iw = fminf(p.z, q.z) - fmaxf(p.x, q.x) + 1.0f;
    float ih = fminf(p.w, q.w) - fmaxf(p.y, q.y) + 1.0f;
    float inter = fmaxf(iw, 0.0f) * fmaxf(ih, 0.0f);
    float u = ap + aq - inter;
    float diff = inter - NMS_TH * u;
    if (fabsf(diff) > 1e-5f * u) return diff > 0.0f;
    return (inter / u) > NMS_TH;
}

__global__ void __launch_bounds__(NTHREADS, 1)
proposal_kernel(const float* __restrict__ scores,
                const float* __restrict__ deltas,
                const float* __restrict__ im_info,
                float* __restrict__ out)
{
    const unsigned FULL = 0xFFFFFFFFu;
    int b = blockIdx.x;
    int t = threadIdx.x;
    extern __shared__ unsigned char sm[];
    u64*           keys  = (u64*)(sm + SM_KEYS);
    unsigned*      hist  = (unsigned*)(sm + SM_HIST);
    float4*        boxes = (float4*)(sm + SM_BOXES);
    float*         areas = (float*)(sm + SM_AREAS);
    float4*        kbox  = (float4*)(sm + SM_KBOX);
    float*         karea = (float*)(sm + SM_KAREA);
    u64*           rows  = (u64*)(sm + SM_ROWS);
    unsigned char* dead  = (unsigned char*)(sm + SM_DEAD);
    __shared__ int s_Bstar, s_cnt;
    __shared__ typename cub::BlockScan<unsigned, NTHREADS>::TempStorage scan_ts;

    // Pre-fill output rows: [b, 0,0,0,0] (d_out arrives poisoned).
    for (int j = t; j < POST_TOPN * 5; j += NTHREADS) {
        int r = j / 5, cc = j % 5;
        out[((size_t)b * POST_TOPN + r) * 5 + cc] = (cc == 0) ? (float)b : 0.0f;
    }

    // ===================== Phase 1: select top-6000 =========================
    for (int q = t; q < NBUCKET; q += NTHREADS) hist[q] = 0;
    for (int q = t; q < CAP;     q += NTHREADS) keys[q] = ~0ull;
    __syncthreads();

    const float* sc_base = scores + ((size_t)b * 2 * A_NUM + A_NUM) * HW_DIM;

    // Pass A: value-bucket histogram
    for (int m = t; m < N_ANCH; m += NTHREADS)
        atomicAdd(&hist[score_bucket(sc_base[m])], 1u);
    __syncthreads();

    // Exclusive scan over buckets; find cutoff bucket B*.
    unsigned cnt16[16], sum = 0;
    #pragma unroll
    for (int k = 0; k < 16; k++) { cnt16[k] = hist[t * 16 + k]; sum += cnt16[k]; }
    unsigned ex_base;
    cub::BlockScan<unsigned, NTHREADS>(scan_ts).ExclusiveSum(sum, ex_base);
    unsigned run = ex_base;
    #pragma unroll
    for (int k = 0; k < 16; k++) {
        unsigned inc = run + cnt16[k];
        if (run < PRE_TOPN && inc >= PRE_TOPN) s_Bstar = t * 16 + k;
        hist[t * 16 + k] = run;
        run = inc;
    }
    __syncthreads();
    int Bstar = s_Bstar;

    // Pass B: scatter selected keys to their global-rank slot.
    for (int m = t; m < N_ANCH; m += NTHREADS) {
        float sc = sc_base[m];
        int bkt = score_bucket(sc);
        if (bkt <= Bstar) {
            unsigned u = __float_as_uint(sc);
            u = min(u, 0x3F7FFFFFu);
            unsigned d = 0x3F7FFFFFu - u;
            int a = m / HW_DIM, hw = m - a * HW_DIM;
            unsigned idx = (unsigned)(hw * A_NUM + a);   // reference flatten
            int slot = (int)atomicAdd(&hist[bkt], 1u);
            if (slot < CAP) keys[slot] = ((u64)d << 16) | idx;
        }
    }
    __syncthreads();

    // Per-bucket insertion sort by full key (spans ~Poisson(2.1)).
    for (int q = t; q <= Bstar; q += NTHREADS) {
        int start = (q == 0) ? 0 : (int)hist[q - 1];
        int end   = (int)hist[q];
        if (end > CAP) end = CAP;
        for (int x = start + 1; x < end; x++) {
            u64 kx = keys[x];
            int y = x - 1;
            while (y >= start && keys[y] > kx) { keys[y + 1] = keys[y]; y--; }
            keys[y + 1] = kx;
        }
    }
    __syncthreads();   // hist dead from here; boxes region may be written

    // ===================== Phase 2: decode into SMEM ========================
    float imh = im_info[b * 3 + 0];
    float imw = im_info[b * 3 + 1];
    const float* dl = deltas + (size_t)b * 4 * A_NUM * HW_DIM;

    for (int p = t; p < PRE_TOPN; p += NTHREADS) {
        unsigned idx = (unsigned)(keys[p] & 0xFFFFull);
        int a  = idx % A_NUM;
        int hw = idx / A_NUM;
        int w  = hw % W_DIM;
        int h  = hw / W_DIM;

        float sx = (float)(w * 16);
        float sy = (float)(h * 16);
        float ax1 = c_anchors[a * 4 + 0] + sx;
        float ay1 = c_anchors[a * 4 + 1] + sy;
        float ax2 = c_anchors[a * 4 + 2] + sx;
        float ay2 = c_anchors[a * 4 + 3] + sy;

        float wa  = ax2 - ax1 + 1.0f;
        float ha  = ay2 - ay1 + 1.0f;
        float cxa = ax1 + 0.5f * wa;
        float cya = ay1 + 0.5f * ha;

        size_t dbase = (size_t)(a * 4) * HW_DIM + hw;
        float dx = dl[dbase];
        float dy = dl[dbase +     HW_DIM];
        float dw = dl[dbase + 2 * HW_DIM];
        float dh = dl[dbase + 3 * HW_DIM];

        float pcx = dx * wa + cxa;
        float pcy = dy * ha + cya;
        float pw  = expf(dw) * wa;
        float ph  = expf(dh) * ha;

        float x1 = fminf(fmaxf(pcx - 0.5f * pw, 0.0f), imw - 1.0f);
        float y1 = fminf(fmaxf(pcy - 0.5f * ph, 0.0f), imh - 1.0f);
        float x2 = fminf(fmaxf(pcx + 0.5f * pw, 0.0f), imw - 1.0f);
        float y2 = fminf(fmaxf(pcy + 0.5f * ph, 0.0f), imh - 1.0f);

        boxes[p] = make_float4(x1, y1, x2, y2);
        areas[p] = (x2 - x1 + 1.0f) * (y2 - y1 + 1.0f);
    }
    if (t == 0) s_cnt = 0;
    __syncthreads();

    // ===================== Phase 3: chunked greedy NMS ======================
    // Chunk c holds candidates [c*64, c*64+64). A candidate is suppressed iff
    // IoU>0.7 with an earlier KEPT box: earlier chunks -> kept-list test
    // (parallel); same chunk -> 64x64 matrix + sequential bit-propagation
    // (one step per kept box). Exactly reproduces greedy NMS order.
    for (int c = 0; c < NCHUNK; c++) {
        int base   = c * 64;
        int nvalid = min(64, PRE_TOPN - base);
        if (t < 64) dead[t] = (t >= nvalid) ? 1 : 0;
        __syncthreads();                       // S1: dead reset + s_cnt visible
        int kc = s_cnt;

        if (t >= 64) {
            // suppress-by-kept: 15 groups of 64 threads; group g tests kept
            // indices g, g+15, g+30, ... for candidate j = (t-64)&63.
            int j   = (t - 64) & 63;
            int grp = (t - 64) >> 6;
            if (j < nvalid) {
                float4 bj = boxes[base + j];
                float  aj = areas[base + j];
                for (int k = grp; k < kc; k += 15) {
                    if (iou_sup(kbox[k], karea[k], bj, aj)) { dead[j] = 1; break; }
                }
            }
        } else {
            // intra-chunk suppression row for j1 = t
            u64 bits = 0;
            if (t < nvalid) {
                float4 b1 = boxes[base + t];
                float  a1 = areas[base + t];
                for (int j2 = t + 1; j2 < nvalid; j2++) {
                    if (iou_sup(b1, a1, boxes[base + j2], areas[base + j2]))
                        bits |= 1ull << j2;
                }
            }
            rows[t] = bits;
        }
        __syncthreads();                       // S2

        if (t < 32) {
            unsigned lo = __ballot_sync(FULL, dead[t]      == 0);
            unsigned hi = __ballot_sync(FULL, dead[t + 32] == 0);
            if (t == 0) {
                u64 alive = (u64)lo | ((u64)hi << 32);
                int cnt = s_cnt;
                while (alive && cnt < POST_TOPN) {
                    int j = __ffsll((long long)alive) - 1;
                    kbox[cnt]  = boxes[base + j];
                    karea[cnt] = areas[base + j];
                    cnt++;
                    alive &= ~(rows[j] | (1ull << j));
                }
                s_cnt = cnt;
            }
        }
        __syncthreads();                       // S3
        if (s_cnt >= POST_TOPN) break;
    }

    // ===================== Emit kept boxes ==================================
    int total = s_cnt;
    for (int k = t; k < total; k += NTHREADS) {
        float4 v = kbox[k];
        float* o = out + ((size_t)b * POST_TOPN + k) * 5;
        o[1] = v.x; o[2] = v.y; o[3] = v.z; o[4] = v.w;
    }
}

// ---------------------------------------------------------------------------
// Launch: ONE kernel, one CTA per image.
// ---------------------------------------------------------------------------
extern "C" void kernel_launch(void* const* d_in, const int* in_sizes, int n_in,
                              void* d_out, int out_size)
{
    const float* scores  = (const float*)d_in[0];   // (4, 18, 50, 76)
    const float* deltas  = (const float*)d_in[1];   // (4, 36, 50, 76)
    const float* im_info = (const float*)d_in[2];   // (4, 3)
    float*       out     = (float*)d_out;           // (4, 300, 5)

    cudaFuncSetAttribute(proposal_kernel,
                         cudaFuncAttributeMaxDynamicSharedMemorySize,
                         SM_TOTAL);
    proposal_kernel<<<BATCH, NTHREADS, SM_TOTAL>>>(scores, deltas, im_info, out);
}

// round 13
// speedup vs baseline: 10.3967x; 1.1631x over previous
#include <cuda_runtime.h>
#include <cstdint>
#include <cub/cub.cuh>

// ---------------------------------------------------------------------------
// ProposalLayer: B=4, A=9, H=50, W=76, FEAT_STRIDE=16
// pre-NMS topN = 6000, post-NMS topN = 300, nms thresh = 0.7
// R13 = R12 (98.3us) with a faster NMS phase:
//   - kept-test groups poll a shared dead[] flag (software-pipelined LDS) so
//     all groups abort at the earliest suppressor instead of scanning kc/G
//   - intra-chunk 64x64 matrix split 4 ways per row (serial depth 63 -> ~16)
//   - boxes stored pre-primed (x2+1, y2+1): iw/ih bit-identical with 2 fewer
//     FADDs per IoU; areas computed in reference form BEFORE priming so the
//     exact-division fallback stays bit-identical
// ---------------------------------------------------------------------------

#define BATCH     4
#define A_NUM     9
#define H_DIM     50
#define W_DIM     76
#define HW_DIM    (H_DIM * W_DIM)          // 3800
#define N_ANCH    (A_NUM * HW_DIM)         // 34200
#define PRE_TOPN  6000
#define POST_TOPN 300
#define NMS_TH    0.7f
#define NBUCKET   16384
#define CAP       8192
#define NTHREADS  1024
#define NCHUNK    94                        // ceil(6000/64)
#define KGROUPS   12                        // kept-test groups (768 threads)

typedef unsigned long long u64;

// SMEM layout (dynamic), bytes:
//   [0      , 65536 )  keys   u64[8192]
//   [65536  , 131072)  hist   u32[16384]   (ALIAS: dies before boxes written)
//   [65536  , 161536)  boxes  float4[6000] (primed: z=x2+1, w=y2+1)
//   [161536 , 185536)  areas  float[6000]  (reference form)
//   [185536 , 190336)  kbox   float4[300]
//   [190336 , 191536)  karea  float[300]
//   [191536 , 192048)  rows   u64[64]
//   [192048 , 192112)  dead   uchar[64]
#define SM_KEYS   0
#define SM_HIST   65536
#define SM_BOXES  65536
#define SM_AREAS  161536
#define SM_KBOX   185536
#define SM_KAREA  190336
#define SM_ROWS   191536
#define SM_DEAD   192048
#define SM_TOTAL  192112

// Precomputed generate_anchors(base=16, ratios={0.5,1,2}, scales={8,16,32})
__constant__ float c_anchors[A_NUM * 4] = {
    -84.f,  -40.f,   99.f,   55.f,
   -176.f,  -88.f,  191.f,  103.f,
   -360.f, -184.f,  375.f,  199.f,
    -56.f,  -56.f,   71.f,   71.f,
   -120.f, -120.f,  135.f,  135.f,
   -248.f, -248.f,  263.f,  263.f,
    -36.f,  -80.f,   51.f,   95.f,
    -80.f, -168.f,   95.f,  183.f,
   -168.f, -344.f,  183.f,  359.f
};

// Descending value-bucket: monotone non-decreasing in descending-score order;
// coarse order exact, within-bucket order fixed by the full 46-bit key.
__device__ __forceinline__ int score_bucket(float sc) {
    int f = (int)(sc * (float)NBUCKET);
    f = min(max(f, 0), NBUCKET - 1);
    return (NBUCKET - 1) - f;
}

// Guard-banded IoU > 0.7 on PRIMED boxes (z=x2+1, w=y2+1). iw/ih are
// bit-identical to the reference (min(a+1,b+1) == min(a,b)+1 exactly here);
// areas are reference-form, so the exact fallback divides identical values.
__device__ __forceinline__ bool iou_sup(float4 p, float ap, float4 q, float aq) {
    float iw = fminf(p.z, q.z) - fmaxf(p.x, q.x);
    float ih = fminf(p.w, q.w) - fmaxf(p.y, q.y);
    float inter = fmaxf(iw, 0.0f) * fmaxf(ih, 0.0f);
    float u = ap + aq - inter;
    float diff = inter - NMS_TH * u;
    if (fabsf(diff) > 1e-5f * u) return diff > 0.0f;
    return (inter / u) > NMS_TH;
}

__global__ void __launch_bounds__(NTHREADS, 1)
proposal_kernel(const float* __restrict__ scores,
                const float* __restrict__ deltas,
                const float* __restrict__ im_info,
                float* __restrict__ out)
{
    const unsigned FULL = 0xFFFFFFFFu;
    int b = blockIdx.x;
    int t = threadIdx.x;
    extern __shared__ unsigned char sm[];
    u64*           keys  = (u64*)(sm + SM_KEYS);
    unsigned*      hist  = (unsigned*)(sm + SM_HIST);
    float4*        boxes = (float4*)(sm + SM_BOXES);
    float*         areas = (float*)(sm + SM_AREAS);
    float4*        kbox  = (float4*)(sm + SM_KBOX);
    float*         karea = (float*)(sm + SM_KAREA);
    u64*           rows  = (u64*)(sm + SM_ROWS);
    unsigned char* dead  = (unsigned char*)(sm + SM_DEAD);
    volatile unsigned char* vdead = (volatile unsigned char*)dead;
    __shared__ int s_Bstar, s_cnt;
    __shared__ typename cub::BlockScan<unsigned, NTHREADS>::TempStorage scan_ts;

    // Pre-fill output rows: [b, 0,0,0,0] (d_out arrives poisoned).
    for (int j = t; j < POST_TOPN * 5; j += NTHREADS) {
        int r = j / 5, cc = j % 5;
        out[((size_t)b * POST_TOPN + r) * 5 + cc] = (cc == 0) ? (float)b : 0.0f;
    }

    // ===================== Phase 1: select top-6000 =========================
    for (int q = t; q < NBUCKET; q += NTHREADS) hist[q] = 0;
    for (int q = t; q < CAP;     q += NTHREADS) keys[q] = ~0ull;
    __syncthreads();

    const float* sc_base = scores + ((size_t)b * 2 * A_NUM + A_NUM) * HW_DIM;

    // Pass A: value-bucket histogram
    for (int m = t; m < N_ANCH; m += NTHREADS)
        atomicAdd(&hist[score_bucket(sc_base[m])], 1u);
    __syncthreads();

    // Exclusive scan over buckets; find cutoff bucket B*.
    unsigned cnt16[16], sum = 0;
    #pragma unroll
    for (int k = 0; k < 16; k++) { cnt16[k] = hist[t * 16 + k]; sum += cnt16[k]; }
    unsigned ex_base;
    cub::BlockScan<unsigned, NTHREADS>(scan_ts).ExclusiveSum(sum, ex_base);
    unsigned run = ex_base;
    #pragma unroll
    for (int k = 0; k < 16; k++) {
        unsigned inc = run + cnt16[k];
        if (run < PRE_TOPN && inc >= PRE_TOPN) s_Bstar = t * 16 + k;
        hist[t * 16 + k] = run;
        run = inc;
    }
    __syncthreads();
    int Bstar = s_Bstar;

    // Pass B: scatter selected keys to their global-rank slot.
    for (int m = t; m < N_ANCH; m += NTHREADS) {
        float sc = sc_base[m];
        int bkt = score_bucket(sc);
        if (bkt <= Bstar) {
            unsigned u = __float_as_uint(sc);
            u = min(u, 0x3F7FFFFFu);
            unsigned d = 0x3F7FFFFFu - u;
            int a = m / HW_DIM, hw = m - a * HW_DIM;
            unsigned idx = (unsigned)(hw * A_NUM + a);   // reference flatten
            int slot = (int)atomicAdd(&hist[bkt], 1u);
            if (slot < CAP) keys[slot] = ((u64)d << 16) | idx;
        }
    }
    __syncthreads();

    // Per-bucket insertion sort by full key (spans ~Poisson(2.1)).
    for (int q = t; q <= Bstar; q += NTHREADS) {
        int start = (q == 0) ? 0 : (int)hist[q - 1];
        int end   = (int)hist[q];
        if (end > CAP) end = CAP;
        for (int x = start + 1; x < end; x++) {
            u64 kx = keys[x];
            int y = x - 1;
            while (y >= start && keys[y] > kx) { keys[y + 1] = keys[y]; y--; }
            keys[y + 1] = kx;
        }
    }
    __syncthreads();   // hist dead from here; boxes region may be written

    // ===================== Phase 2: decode into SMEM ========================
    float imh = im_info[b * 3 + 0];
    float imw = im_info[b * 3 + 1];
    const float* dl = deltas + (size_t)b * 4 * A_NUM * HW_DIM;

    for (int p = t; p < PRE_TOPN; p += NTHREADS) {
        unsigned idx = (unsigned)(keys[p] & 0xFFFFull);
        int a  = idx % A_NUM;
        int hw = idx / A_NUM;
        int w  = hw % W_DIM;
        int h  = hw / W_DIM;

        float sx = (float)(w * 16);
        float sy = (float)(h * 16);
        float ax1 = c_anchors[a * 4 + 0] + sx;
        float ay1 = c_anchors[a * 4 + 1] + sy;
        float ax2 = c_anchors[a * 4 + 2] + sx;
        float ay2 = c_anchors[a * 4 + 3] + sy;

        float wa  = ax2 - ax1 + 1.0f;
        float ha  = ay2 - ay1 + 1.0f;
        float cxa = ax1 + 0.5f * wa;
        float cya = ay1 + 0.5f * ha;

        size_t dbase = (size_t)(a * 4) * HW_DIM + hw;
        float dx = dl[dbase];
        float dy = dl[dbase +     HW_DIM];
        float dw = dl[dbase + 2 * HW_DIM];
        float dh = dl[dbase + 3 * HW_DIM];

        float pcx = dx * wa + cxa;
        float pcy = dy * ha + cya;
        float pw  = expf(dw) * wa;
        float ph  = expf(dh) * ha;

        float x1 = fminf(fmaxf(pcx - 0.5f * pw, 0.0f), imw - 1.0f);
        float y1 = fminf(fmaxf(pcy - 0.5f * ph, 0.0f), imh - 1.0f);
        float x2 = fminf(fmaxf(pcx + 0.5f * pw, 0.0f), imw - 1.0f);
        float y2 = fminf(fmaxf(pcy + 0.5f * ph, 0.0f), imh - 1.0f);

        // reference-form area FIRST, then primed box (x2+1 exact in fp32)
        areas[p] = (x2 - x1 + 1.0f) * (y2 - y1 + 1.0f);
        boxes[p] = make_float4(x1, y1, x2 + 1.0f, y2 + 1.0f);
    }
    if (t == 0) s_cnt = 0;
    __syncthreads();

    // ===================== Phase 3: chunked greedy NMS ======================
    // Chunk c = candidates [c*64, c*64+64). Suppressed iff IoU>0.7 with an
    // earlier kept box: earlier chunks -> kept-list test (12 groups x 64, with
    // cross-group early-abort via dead[] polling); same chunk -> 64x64 matrix
    // (4 threads/row, shfl-combined) + sequential bit-propagation by t0.
    for (int c = 0; c < NCHUNK; c++) {
        int base   = c * 64;
        int nvalid = min(64, PRE_TOPN - base);
        if (t < 64) dead[t] = (t >= nvalid) ? 1 : 0;
        __syncthreads();                       // S1: dead reset + s_cnt visible
        int kc = s_cnt;

        if (t >= 256) {
            // kept-test: 12 groups of 64 threads; group g tests kept indices
            // g, g+12, g+24, ... for candidate j = (t-256)&63. A dead[] read
            // is software-pipelined ahead of each IoU so all groups abort
            // shortly after ANY group finds a suppressor.
            int j   = (t - 256) & 63;
            int grp = (t - 256) >> 6;
            if (j < nvalid && kc > 0) {
                float4 bj = boxes[base + j];
                float  aj = areas[base + j];
                for (int k = grp; k < kc; k += KGROUPS) {
                    unsigned char d = vdead[j];          // overlaps IoU math
                    if (iou_sup(kbox[k], karea[k], bj, aj)) { dead[j] = 1; break; }
                    if (d) break;
                }
            }
        } else {
            // intra-chunk matrix: 4 threads per row, strided columns,
            // OR-combined via shfl_xor (lanes row*4+sub within each warp)
            int sub = t & 3;
            int row = t >> 2;                  // 0..63
            u64 bits = 0;
            if (row < nvalid) {
                float4 b1 = boxes[base + row];
                float  a1 = areas[base + row];
                for (int j2 = row + 1 + sub; j2 < nvalid; j2 += 4) {
                    if (iou_sup(b1, a1, boxes[base + j2], areas[base + j2]))
                        bits |= 1ull << j2;
                }
            }
            bits |= __shfl_xor_sync(FULL, bits, 1);
            bits |= __shfl_xor_sync(FULL, bits, 2);
            if (sub == 0 && row < 64) rows[row] = bits;
        }
        __syncthreads();                       // S2

        if (t < 32) {
            unsigned lo = __ballot_sync(FULL, dead[t]      == 0);
            unsigned hi = __ballot_sync(FULL, dead[t + 32] == 0);
            if (t == 0) {
                u64 alive = (u64)lo | ((u64)hi << 32);
                int cnt = s_cnt;
                while (alive && cnt < POST_TOPN) {
                    int j = __ffsll((long long)alive) - 1;
                    kbox[cnt]  = boxes[base + j];
                    karea[cnt] = areas[base + j];
                    cnt++;
                    alive &= ~(rows[j] | (1ull << j));
                }
                s_cnt = cnt;
            }
        }
        __syncthreads();                       // S3
        if (s_cnt >= POST_TOPN) break;
    }

    // ===================== Emit kept boxes (un-prime x2,y2) =================
    int total = s_cnt;
    for (int k = t; k < total; k += NTHREADS) {
        float4 v = kbox[k];
        float* o = out + ((size_t)b * POST_TOPN + k) * 5;
        o[1] = v.x; o[2] = v.y; o[3] = v.z - 1.0f; o[4] = v.w - 1.0f;
    }
}

// ---------------------------------------------------------------------------
// Launch: ONE kernel, one CTA per image.
// ---------------------------------------------------------------------------
extern "C" void kernel_launch(void* const* d_in, const int* in_sizes, int n_in,
                              void* d_out, int out_size)
{
    const float* scores  = (const float*)d_in[0];   // (4, 18, 50, 76)
    const float* deltas  = (const float*)d_in[1];   // (4, 36, 50, 76)
    const float* im_info = (const float*)d_in[2];   // (4, 3)
    float*       out     = (float*)d_out;           // (4, 300, 5)

    cudaFuncSetAttribute(proposal_kernel,
                         cudaFuncAttributeMaxDynamicSharedMemorySize,
                         SM_TOTAL);
    proposal_kernel<<<BATCH, NTHREADS, SM_TOTAL>>>(scores, deltas, im_info, out);
}